// round 13
// baseline (speedup 1.0000x reference)
#include <cuda_runtime.h>

// Problem constants (fixed by reference setup_inputs)
#define N_NODES 100000
#define E_EDGES 1600000
#define F0 128
#define F1 64
#define F2 40

// ---------------- static scratch (no allocations allowed) ----------------
// g_deg / g_cnt start zero (static init) and are re-zeroed by k_scan_one
// after use, so every replay sees them zeroed. No init kernel needed.
__device__ int   g_is64;                // edge_index dtype flag (device-detected)
__device__ float g_deg[N_NODES];        // edge-weight sum per dst (self-loop added later)
__device__ float g_dinv[N_NODES];
__device__ int   g_src[E_EDGES];
__device__ int   g_dst[E_EDGES];
__device__ int   g_cnt[N_NODES];        // per-dst edge count
__device__ int   g_row_start[N_NODES + 1];
__device__ int   g_cursor[N_NODES];
__device__ int2  g_csr[E_EDGES];        // packed {src, norm_bits}, grouped by dst
__device__ float g_h1[(size_t)N_NODES * F1];    // x @ W1
__device__ float g_agg1[(size_t)N_NODES * F1];  // gathered + bias + relu
__device__ float g_h2[(size_t)N_NODES * F2];    // agg1 @ W2

// ---------------- dtype sniff: int64 edge_index has all-zero odd 32-bit words ----------------
__global__ void k_sniff(const int* __restrict__ ei32) {
    int lane = threadIdx.x;
    int any = 0;
#pragma unroll
    for (int k = 0; k < 32; k++)
        any |= ei32[2 * (lane + 32 * k) + 1];     // 32 lanes x 32 = 1024 samples
    unsigned b = __ballot_sync(0xffffffffu, any != 0);
    if (lane == 0) g_is64 = (b == 0u) ? 1 : 0;
}

// ---------------- edge pass: decode (either dtype), degree + count (deg/cnt pre-zeroed) ----------------
__global__ void k_edge_prep(const int* __restrict__ ei32,
                            const float* __restrict__ w, int E, int n) {
    int e = blockIdx.x * blockDim.x + threadIdx.x;
    if (e >= E) return;
    int s, d;
    if (g_is64) {                                  // int64, little-endian low words
        s = ei32[2 * (size_t)e];
        d = ei32[2 * ((size_t)E + e)];
    } else {                                       // int32
        s = ei32[e];
        d = ei32[(size_t)E + e];
    }
    if ((unsigned)s >= (unsigned)n) s = 0;         // safety clamp
    if ((unsigned)d >= (unsigned)n) d = 0;
    g_src[e] = s;
    g_dst[e] = d;
    atomicAdd(&g_deg[d], w[e]);
    atomicAdd(&g_cnt[d], 1);
}

// ---------------- single-block exclusive scan of g_cnt + dinv + deferred re-zero ----------------
// One block of 1024 threads walks n in chunks; shfl warp scans (2 syncs/chunk).
// Also: dinv = rsqrt(deg + 1)  (self-loop weight 1 folded in; deg+1 > 0 always),
// and zeroes deg/cnt so the NEXT replay's edge_prep starts clean.
__global__ void k_scan_one(int n, int E) {
    __shared__ int wsum[32];
    __shared__ int chunk_carry;
    int tid  = threadIdx.x;
    int lane = tid & 31;
    int wid  = tid >> 5;
    if (tid == 0) chunk_carry = 0;
    __syncthreads();

    for (int base = 0; base < n; base += 1024) {
        int i = base + tid;
        int v = (i < n) ? g_cnt[i] : 0;
        if (i < n) {
            g_dinv[i] = rsqrtf(g_deg[i] + 1.0f);
            g_deg[i] = 0.f;          // deferred zero for next replay
            g_cnt[i] = 0;
        }
        // warp inclusive scan
        int x = v;
#pragma unroll
        for (int off = 1; off < 32; off <<= 1) {
            int y = __shfl_up_sync(0xffffffffu, x, off);
            if (lane >= off) x += y;
        }
        if (lane == 31) wsum[wid] = x;
        __syncthreads();
        if (wid == 0) {
            int s = wsum[lane];
#pragma unroll
            for (int off = 1; off < 32; off <<= 1) {
                int y = __shfl_up_sync(0xffffffffu, s, off);
                if (lane >= off) s += y;
            }
            wsum[lane] = s;          // inclusive warp-sum scan
        }
        __syncthreads();
        int woff  = (wid == 0) ? 0 : wsum[wid - 1];
        int incl  = x + woff;
        int total = wsum[31];
        if (i < n) {
            int rs = chunk_carry + incl - v;   // exclusive prefix
            g_row_start[i] = rs;
            g_cursor[i]    = rs;
        }
        __syncthreads();             // all reads of chunk_carry done
        if (tid == 0) chunk_carry += total;
        __syncthreads();
    }
    if (tid == 0) g_row_start[n] = E;
}

// ---------------- fill CSR: grouped-by-dst packed (src, norm) — PROFILED at launch idx 3 ----------------
__global__ void k_fill(const float* __restrict__ w, int E) {
    int e = blockIdx.x * blockDim.x + threadIdx.x;
    if (e >= E) return;
    int s = g_src[e];
    int d = g_dst[e];
    float nv = g_dinv[s] * w[e] * g_dinv[d];
    int pos = atomicAdd(&g_cursor[d], 1);
    if (pos >= 0 && pos < E) g_csr[pos] = make_int2(s, __float_as_int(nv));
}

// ---------------- R6 register-blocked fp32 GEMM (best-known config) ----------------
template <int KDIM, int NC, int RPB>
__global__ void k_gemm(const float* __restrict__ A, const float* __restrict__ W,
                       float* __restrict__ C, int nrows) {
    constexpr int TC = NC / 8;
    constexpr int APAD = KDIM + 4;
    __shared__ float Ws[KDIM * NC];
    __shared__ float As[RPB * APAD];

    int tid = threadIdx.x;
    int nthr = blockDim.x;

    for (int i = tid; i < KDIM * NC / 4; i += nthr)
        ((float4*)Ws)[i] = ((const float4*)W)[i];

    int row0 = blockIdx.x * RPB;
    for (int i = tid; i < RPB * (KDIM / 4); i += nthr) {
        int r = i / (KDIM / 4);
        int kc = i % (KDIM / 4);
        int grow = row0 + r;
        float4 v = make_float4(0.f, 0.f, 0.f, 0.f);
        if (grow < nrows) v = ((const float4*)(A + (size_t)grow * KDIM))[kc];
        *(float4*)&As[r * APAD + kc * 4] = v;
    }
    __syncthreads();

    int r  = tid / TC;
    int c0 = (tid % TC) * 8;
    float acc[8];
#pragma unroll
    for (int j = 0; j < 8; j++) acc[j] = 0.f;

#pragma unroll 8
    for (int k = 0; k < KDIM; k++) {
        float a = As[r * APAD + k];
        float4 w0 = *(const float4*)&Ws[k * NC + c0];
        float4 w1 = *(const float4*)&Ws[k * NC + c0 + 4];
        acc[0] = fmaf(a, w0.x, acc[0]);
        acc[1] = fmaf(a, w0.y, acc[1]);
        acc[2] = fmaf(a, w0.z, acc[2]);
        acc[3] = fmaf(a, w0.w, acc[3]);
        acc[4] = fmaf(a, w1.x, acc[4]);
        acc[5] = fmaf(a, w1.y, acc[5]);
        acc[6] = fmaf(a, w1.z, acc[6]);
        acc[7] = fmaf(a, w1.w, acc[7]);
    }

    int grow = row0 + r;
    if (grow < nrows) {
        float4* op = (float4*)(C + (size_t)grow * NC + c0);
        op[0] = make_float4(acc[0], acc[1], acc[2], acc[3]);
        op[1] = make_float4(acc[4], acc[5], acc[6], acc[7]);
    }
}

// ---------------- CSR gather (R6 2-deep config): out[row] = sum h[src]*norm
//                  + h[row]*dinv^2 + bias (+relu). thread = (node, float4-col).
template <int NC4, bool RELU>
__global__ void k_gather(const float* __restrict__ h, const float* __restrict__ bias,
                         float* __restrict__ out, int n) {
    int tid = blockIdx.x * blockDim.x + threadIdx.x;
    if (tid >= n * NC4) return;
    int row = tid / NC4;
    int c   = tid % NC4;

    const float4* h4 = (const float4*)h;
    float di = g_dinv[row];
    float s2 = di * di;

    float4 self = h4[(size_t)row * NC4 + c];
    float4 acc = make_float4(self.x * s2, self.y * s2, self.z * s2, self.w * s2);

    int beg = g_row_start[row];
    int end = g_row_start[row + 1];

    int j = beg;
    for (; j + 1 < end; j += 2) {
        int2 p0 = g_csr[j];
        int2 p1 = g_csr[j + 1];
        float4 v0 = h4[(size_t)p0.x * NC4 + c];
        float4 v1 = h4[(size_t)p1.x * NC4 + c];
        float nv0 = __int_as_float(p0.y);
        float nv1 = __int_as_float(p1.y);
        acc.x = fmaf(v0.x, nv0, acc.x); acc.y = fmaf(v0.y, nv0, acc.y);
        acc.z = fmaf(v0.z, nv0, acc.z); acc.w = fmaf(v0.w, nv0, acc.w);
        acc.x = fmaf(v1.x, nv1, acc.x); acc.y = fmaf(v1.y, nv1, acc.y);
        acc.z = fmaf(v1.z, nv1, acc.z); acc.w = fmaf(v1.w, nv1, acc.w);
    }
    if (j < end) {
        int2 p = g_csr[j];
        float nv = __int_as_float(p.y);
        float4 v = h4[(size_t)p.x * NC4 + c];
        acc.x = fmaf(v.x, nv, acc.x); acc.y = fmaf(v.y, nv, acc.y);
        acc.z = fmaf(v.z, nv, acc.z); acc.w = fmaf(v.w, nv, acc.w);
    }

    float4 b = ((const float4*)bias)[c];
    acc.x += b.x; acc.y += b.y; acc.z += b.z; acc.w += b.w;
    if (RELU) {
        acc.x = fmaxf(acc.x, 0.f); acc.y = fmaxf(acc.y, 0.f);
        acc.z = fmaxf(acc.z, 0.f); acc.w = fmaxf(acc.w, 0.f);
    }
    ((float4*)out)[(size_t)row * NC4 + c] = acc;
}

// ---------------- finalize: log_softmax in place, one warp per row ----------------
__global__ void k_finalize(float* __restrict__ out, int n) {
    int row = blockIdx.x * blockDim.y + threadIdx.y;
    if (row >= n) return;
    int lane = threadIdx.x;
    float* orow = out + (size_t)row * F2;

    float v0 = orow[lane];
    float v1 = 0.f;
    bool has2 = (lane < F2 - 32);
    if (has2) v1 = orow[lane + 32];

    float m = v0;
    if (has2) m = fmaxf(m, v1);
#pragma unroll
    for (int off = 16; off > 0; off >>= 1)
        m = fmaxf(m, __shfl_xor_sync(0xffffffffu, m, off));

    float s = expf(v0 - m);
    if (has2) s += expf(v1 - m);
#pragma unroll
    for (int off = 16; off > 0; off >>= 1)
        s += __shfl_xor_sync(0xffffffffu, s, off);

    float lse = m + logf(s);
    orow[lane] = v0 - lse;
    if (has2) orow[lane + 32] = v1 - lse;
}

// ---------------- host launcher ----------------
extern "C" void kernel_launch(void* const* d_in, const int* in_sizes, int n_in,
                              void* d_out, int out_size) {
    // Identify inputs by element count (all 7 distinct), robust to metadata order:
    //   x=N*128 (largest), edge_index=2E, edge_weight=E, W1=8192, W2=2560, b1=64, b2=40
    int order[16];
    for (int i = 0; i < n_in; i++) order[i] = i;
    for (int a = 0; a < n_in; a++)
        for (int bidx = a + 1; bidx < n_in; bidx++)
            if (in_sizes[order[bidx]] > in_sizes[order[a]]) {
                int t = order[a]; order[a] = order[bidx]; order[bidx] = t;
            }

    const float* x   = (const float*)d_in[order[0]];
    const int*   ei  = (const int*)  d_in[order[1]];   // int32 view; dtype sniffed on device
    const float* w   = (const float*)d_in[order[2]];
    const float* W1  = (const float*)d_in[order[3]];
    const float* W2  = (const float*)d_in[order[4]];
    const float* b1  = (const float*)d_in[order[5]];
    const float* b2  = (const float*)d_in[order[6]];
    float* out = (float*)d_out;

    int N = in_sizes[order[0]] / F0;   // 100000
    int E = in_sizes[order[2]];        // 1600000
    if (N > N_NODES) N = N_NODES;
    if (E > E_EDGES) E = E_EDGES;

    const int T = 256;

    k_sniff<<<1, 32>>>(ei);                                                  // 0
    k_edge_prep<<<(E + T - 1) / T, T>>>(ei, w, E, N);                        // 1
    k_scan_one<<<1, 1024>>>(N, E);                                           // 2
    k_fill<<<(E + T - 1) / T, T>>>(w, E);                                    // 3  <- ncu capture
    k_gemm<F0, F1, 16><<<(N + 15) / 16, 16 * (F1 / 8)>>>(x, W1, g_h1, N);    // 4
    k_gather<F1 / 4, true><<<(N * (F1 / 4) + T - 1) / T, T>>>(g_h1, b1, g_agg1, N);  // 5
    k_gemm<F1, F2, 32><<<(N + 31) / 32, 32 * (F2 / 8)>>>(g_agg1, W2, g_h2, N);       // 6
    k_gather<F2 / 4, false><<<(N * (F2 / 4) + T - 1) / T, T>>>(g_h2, b2, out, N);    // 7
    k_finalize<<<(N + 3) / 4, dim3(32, 4)>>>(out, N);                        // 8
}

// round 14
// speedup vs baseline: 1.5539x; 1.5539x over previous
#include <cuda_runtime.h>

// Problem constants (fixed by reference setup_inputs)
#define N_NODES 100000
#define E_EDGES 1600000
#define F0 128
#define F1 64
#define F2 40

// ---------------- static scratch (no allocations allowed) ----------------
// g_deg / g_cnt start zero (static init) and are re-zeroed by k_scan1 after
// consuming them, so every replay sees them zeroed. No init kernel needed.
__device__ int   g_is64;                // edge_index dtype flag (device-detected)
__device__ float g_deg[N_NODES];        // edge-weight sum per dst (self-loop folded via +1)
__device__ float g_dinv[N_NODES];
__device__ int   g_src[E_EDGES];
__device__ int   g_dst[E_EDGES];
__device__ int   g_cnt[N_NODES];        // per-dst edge count
__device__ int   g_rs_part[N_NODES];    // block-local exclusive scan
__device__ int   g_bsum[128];           // per-block totals
__device__ int   g_row_start[N_NODES + 1];
__device__ int   g_cursor[N_NODES];
__device__ int2  g_csr[E_EDGES];        // packed {src, norm_bits}, grouped by dst
__device__ float g_h1[(size_t)N_NODES * F1];    // x @ W1
__device__ float g_h2[(size_t)N_NODES * F2];    // relu(agg1) @ W2  (written by fused kernel)

// ---------------- dtype sniff: int64 edge_index has all-zero odd 32-bit words ----------------
__global__ void k_sniff(const int* __restrict__ ei32) {
    int lane = threadIdx.x;
    int any = 0;
#pragma unroll
    for (int k = 0; k < 32; k++)
        any |= ei32[2 * (lane + 32 * k) + 1];     // 32 lanes x 32 = 1024 samples
    unsigned b = __ballot_sync(0xffffffffu, any != 0);
    if (lane == 0) g_is64 = (b == 0u) ? 1 : 0;
}

// ---------------- edge pass: decode (either dtype), degree + count (pre-zeroed) ----------------
__global__ void k_edge_prep(const int* __restrict__ ei32,
                            const float* __restrict__ w, int E, int n) {
    int e = blockIdx.x * blockDim.x + threadIdx.x;
    if (e >= E) return;
    int s, d;
    if (g_is64) {                                  // int64, little-endian low words
        s = ei32[2 * (size_t)e];
        d = ei32[2 * ((size_t)E + e)];
    } else {                                       // int32
        s = ei32[e];
        d = ei32[(size_t)E + e];
    }
    if ((unsigned)s >= (unsigned)n) s = 0;         // safety clamp
    if ((unsigned)d >= (unsigned)n) d = 0;
    g_src[e] = s;
    g_dst[e] = d;
    atomicAdd(&g_deg[d], w[e]);
    atomicAdd(&g_cnt[d], 1);
}

// ---------------- scan1: block-local exclusive scan of cnt + dinv + deferred re-zero ----------------
__global__ void k_scan1(int n) {
    __shared__ int sh[1024];
    int i = blockIdx.x * 1024 + threadIdx.x;

    int v = 0;
    if (i < n) {
        v = g_cnt[i];
        g_dinv[i] = rsqrtf(g_deg[i] + 1.0f);   // self-loop weight 1 folded in; always > 0
        g_deg[i] = 0.f;                        // deferred zero for next replay
        g_cnt[i] = 0;
    }
    sh[threadIdx.x] = v;
    __syncthreads();
    for (int off = 1; off < 1024; off <<= 1) {
        int t = 0;
        if (threadIdx.x >= off) t = sh[threadIdx.x - off];
        __syncthreads();
        sh[threadIdx.x] += t;
        __syncthreads();
    }
    int incl = sh[threadIdx.x];
    if (i < n) g_rs_part[i] = incl - v;        // exclusive within block
    if (threadIdx.x == 1023) g_bsum[blockIdx.x] = incl;
}

// ---------------- scan2: parallel exclusive scan of <=128 block sums ----------------
__global__ void k_scan2(int nb) {
    __shared__ int sh[128];
    int t = threadIdx.x;
    int v = (t < nb) ? g_bsum[t] : 0;
    sh[t] = v;
    __syncthreads();
    for (int off = 1; off < 128; off <<= 1) {
        int u = 0;
        if (t >= off) u = sh[t - off];
        __syncthreads();
        sh[t] += u;
        __syncthreads();
    }
    if (t < nb) g_bsum[t] = sh[t] - v;         // exclusive
}

__global__ void k_scan3(int n, int E) {
    int i = blockIdx.x * blockDim.x + threadIdx.x;
    if (i < n) {
        int rs = g_rs_part[i] + g_bsum[i >> 10];
        g_row_start[i] = rs;
        g_cursor[i] = rs;
    }
    if (i == 0) g_row_start[n] = E;
}

// ---------------- fill CSR: grouped-by-dst packed (src, norm) — measured 31us ----------------
__global__ void k_fill(const float* __restrict__ w, int E) {
    int e = blockIdx.x * blockDim.x + threadIdx.x;
    if (e >= E) return;
    int s = g_src[e];
    int d = g_dst[e];
    float nv = g_dinv[s] * w[e] * g_dinv[d];
    int pos = atomicAdd(&g_cursor[d], 1);
    if (pos >= 0 && pos < E) g_csr[pos] = make_int2(s, __float_as_int(nv));
}

// ---------------- R6 register-blocked fp32 GEMM (profiled at launch index 3) ----------------
template <int KDIM, int NC, int RPB>
__global__ void k_gemm(const float* __restrict__ A, const float* __restrict__ W,
                       float* __restrict__ C, int nrows) {
    constexpr int TC = NC / 8;
    constexpr int APAD = KDIM + 4;
    __shared__ float Ws[KDIM * NC];
    __shared__ float As[RPB * APAD];

    int tid = threadIdx.x;
    int nthr = blockDim.x;

    for (int i = tid; i < KDIM * NC / 4; i += nthr)
        ((float4*)Ws)[i] = ((const float4*)W)[i];

    int row0 = blockIdx.x * RPB;
    for (int i = tid; i < RPB * (KDIM / 4); i += nthr) {
        int r = i / (KDIM / 4);
        int kc = i % (KDIM / 4);
        int grow = row0 + r;
        float4 v = make_float4(0.f, 0.f, 0.f, 0.f);
        if (grow < nrows) v = ((const float4*)(A + (size_t)grow * KDIM))[kc];
        *(float4*)&As[r * APAD + kc * 4] = v;
    }
    __syncthreads();

    int r  = tid / TC;
    int c0 = (tid % TC) * 8;
    float acc[8];
#pragma unroll
    for (int j = 0; j < 8; j++) acc[j] = 0.f;

#pragma unroll 8
    for (int k = 0; k < KDIM; k++) {
        float a = As[r * APAD + k];
        float4 w0 = *(const float4*)&Ws[k * NC + c0];
        float4 w1 = *(const float4*)&Ws[k * NC + c0 + 4];
        acc[0] = fmaf(a, w0.x, acc[0]);
        acc[1] = fmaf(a, w0.y, acc[1]);
        acc[2] = fmaf(a, w0.z, acc[2]);
        acc[3] = fmaf(a, w0.w, acc[3]);
        acc[4] = fmaf(a, w1.x, acc[4]);
        acc[5] = fmaf(a, w1.y, acc[5]);
        acc[6] = fmaf(a, w1.z, acc[6]);
        acc[7] = fmaf(a, w1.w, acc[7]);
    }

    int grow = row0 + r;
    if (grow < nrows) {
        float4* op = (float4*)(C + (size_t)grow * NC + c0);
        op[0] = make_float4(acc[0], acc[1], acc[2], acc[3]);
        op[1] = make_float4(acc[4], acc[5], acc[6], acc[7]);
    }
}

// ---------------- FUSED: gather1 + self-loop + bias + relu -> smem -> GEMM2 -> g_h2
// Block = 128 threads = 16 nodes x 8 col-groups (8 floats each).
// Gather phase: 4-deep MLP, 2 float4 loads per edge (8 loads in flight).
// agg rows staged in shared (never hit global). GEMM2 from shared, W2 in shared.
__global__ void __launch_bounds__(128)
k_gather_gemm2(const float* __restrict__ h, const float* __restrict__ b1,
               const float* __restrict__ W2, int n) {
    __shared__ float W2s[F1 * F2];           // 64x40 = 10240B
    __shared__ float As[16][72];             // agg rows; stride 72 (288B, 16B-aligned)

    int tid  = threadIdx.x;
    int node = tid >> 3;                     // 0..15
    int cg   = tid & 7;                      // 0..7
    int row  = blockIdx.x * 16 + node;
    bool valid = (row < n);

    // load W2 (640 float4 / 128 thr = 5 each)
#pragma unroll
    for (int i = tid; i < F1 * F2 / 4; i += 128)
        ((float4*)W2s)[i] = ((const float4*)W2)[i];

    // ---- gather phase ----
    const float4* h4 = (const float4*)h;
    int c0 = cg * 2;                         // float4 col index (2 per thread)
    float4 acc0 = make_float4(0.f, 0.f, 0.f, 0.f);
    float4 acc1 = acc0;

    if (valid) {
        float di = g_dinv[row];
        float s2 = di * di;
        const float4* selfp = h4 + (size_t)row * (F1 / 4) + c0;
        float4 sa = selfp[0], sb = selfp[1];
        acc0 = make_float4(sa.x * s2, sa.y * s2, sa.z * s2, sa.w * s2);
        acc1 = make_float4(sb.x * s2, sb.y * s2, sb.z * s2, sb.w * s2);

        int beg = g_row_start[row];
        int end = g_row_start[row + 1];
        int j = beg;
        for (; j + 4 <= end; j += 4) {       // 4 edges x 2 float4 = 8 loads in flight
            int2 p[4];
            float4 va[4], vb[4];
#pragma unroll
            for (int q = 0; q < 4; q++) p[q] = g_csr[j + q];
#pragma unroll
            for (int q = 0; q < 4; q++) {
                const float4* r = h4 + (size_t)p[q].x * (F1 / 4) + c0;
                va[q] = r[0]; vb[q] = r[1];
            }
#pragma unroll
            for (int q = 0; q < 4; q++) {
                float nv = __int_as_float(p[q].y);
                acc0.x = fmaf(va[q].x, nv, acc0.x); acc0.y = fmaf(va[q].y, nv, acc0.y);
                acc0.z = fmaf(va[q].z, nv, acc0.z); acc0.w = fmaf(va[q].w, nv, acc0.w);
                acc1.x = fmaf(vb[q].x, nv, acc1.x); acc1.y = fmaf(vb[q].y, nv, acc1.y);
                acc1.z = fmaf(vb[q].z, nv, acc1.z); acc1.w = fmaf(vb[q].w, nv, acc1.w);
            }
        }
        for (; j < end; j++) {
            int2 p = g_csr[j];
            float nv = __int_as_float(p.y);
            const float4* r = h4 + (size_t)p.x * (F1 / 4) + c0;
            float4 va = r[0], vb = r[1];
            acc0.x = fmaf(va.x, nv, acc0.x); acc0.y = fmaf(va.y, nv, acc0.y);
            acc0.z = fmaf(va.z, nv, acc0.z); acc0.w = fmaf(va.w, nv, acc0.w);
            acc1.x = fmaf(vb.x, nv, acc1.x); acc1.y = fmaf(vb.y, nv, acc1.y);
            acc1.z = fmaf(vb.z, nv, acc1.z); acc1.w = fmaf(vb.w, nv, acc1.w);
        }

        // bias + relu
        float4 ba = ((const float4*)b1)[c0];
        float4 bb = ((const float4*)b1)[c0 + 1];
        acc0.x = fmaxf(acc0.x + ba.x, 0.f); acc0.y = fmaxf(acc0.y + ba.y, 0.f);
        acc0.z = fmaxf(acc0.z + ba.z, 0.f); acc0.w = fmaxf(acc0.w + ba.w, 0.f);
        acc1.x = fmaxf(acc1.x + bb.x, 0.f); acc1.y = fmaxf(acc1.y + bb.y, 0.f);
        acc1.z = fmaxf(acc1.z + bb.z, 0.f); acc1.w = fmaxf(acc1.w + bb.w, 0.f);
    }
    // stage agg row in shared (zeros for invalid rows are harmless)
    *(float4*)&As[node][cg * 8]     = acc0;
    *(float4*)&As[node][cg * 8 + 4] = acc1;
    __syncthreads();

    // ---- GEMM2 phase: h2[row, c] = As[node][:] @ W2s[:, c], c = cg*5 .. cg*5+4 ----
    float o[5] = {0.f, 0.f, 0.f, 0.f, 0.f};
    int cb = cg * 5;
#pragma unroll 8
    for (int k = 0; k < F1; k++) {
        float a = As[node][k];
        const float* wr = &W2s[k * F2 + cb];
        o[0] = fmaf(a, wr[0], o[0]);
        o[1] = fmaf(a, wr[1], o[1]);
        o[2] = fmaf(a, wr[2], o[2]);
        o[3] = fmaf(a, wr[3], o[3]);
        o[4] = fmaf(a, wr[4], o[4]);
    }
    if (valid) {
        float* op = g_h2 + (size_t)row * F2 + cb;
        op[0] = o[0]; op[1] = o[1]; op[2] = o[2]; op[3] = o[3]; op[4] = o[4];
    }
}

// ---------------- gather2 (4-deep MLP): out[row] = sum h2[src]*norm + h2[row]*dinv^2 + b2 ----------------
__global__ void k_gather2(const float* __restrict__ bias, float* __restrict__ out, int n) {
    constexpr int NC4 = F2 / 4;              // 10
    int tid = blockIdx.x * blockDim.x + threadIdx.x;
    if (tid >= n * NC4) return;
    int row = tid / NC4;
    int c   = tid % NC4;

    const float4* h4 = (const float4*)g_h2;
    float di = g_dinv[row];
    float s2 = di * di;

    float4 self = h4[(size_t)row * NC4 + c];
    float4 acc = make_float4(self.x * s2, self.y * s2, self.z * s2, self.w * s2);

    int beg = g_row_start[row];
    int end = g_row_start[row + 1];
    int j = beg;
    for (; j + 4 <= end; j += 4) {
        int2   p[4];
        float4 v[4];
#pragma unroll
        for (int q = 0; q < 4; q++) p[q] = g_csr[j + q];
#pragma unroll
        for (int q = 0; q < 4; q++) v[q] = h4[(size_t)p[q].x * NC4 + c];
#pragma unroll
        for (int q = 0; q < 4; q++) {
            float nv = __int_as_float(p[q].y);
            acc.x = fmaf(v[q].x, nv, acc.x); acc.y = fmaf(v[q].y, nv, acc.y);
            acc.z = fmaf(v[q].z, nv, acc.z); acc.w = fmaf(v[q].w, nv, acc.w);
        }
    }
    for (; j < end; j++) {
        int2 p = g_csr[j];
        float nv = __int_as_float(p.y);
        float4 v = h4[(size_t)p.x * NC4 + c];
        acc.x = fmaf(v.x, nv, acc.x); acc.y = fmaf(v.y, nv, acc.y);
        acc.z = fmaf(v.z, nv, acc.z); acc.w = fmaf(v.w, nv, acc.w);
    }

    float4 b = ((const float4*)bias)[c];
    acc.x += b.x; acc.y += b.y; acc.z += b.z; acc.w += b.w;
    ((float4*)out)[(size_t)row * NC4 + c] = acc;
}

// ---------------- finalize: log_softmax in place, one warp per row ----------------
__global__ void k_finalize(float* __restrict__ out, int n) {
    int row = blockIdx.x * blockDim.y + threadIdx.y;
    if (row >= n) return;
    int lane = threadIdx.x;
    float* orow = out + (size_t)row * F2;

    float v0 = orow[lane];
    float v1 = 0.f;
    bool has2 = (lane < F2 - 32);
    if (has2) v1 = orow[lane + 32];

    float m = v0;
    if (has2) m = fmaxf(m, v1);
#pragma unroll
    for (int off = 16; off > 0; off >>= 1)
        m = fmaxf(m, __shfl_xor_sync(0xffffffffu, m, off));

    float s = expf(v0 - m);
    if (has2) s += expf(v1 - m);
#pragma unroll
    for (int off = 16; off > 0; off >>= 1)
        s += __shfl_xor_sync(0xffffffffu, s, off);

    float lse = m + logf(s);
    orow[lane] = v0 - lse;
    if (has2) orow[lane + 32] = v1 - lse;
}

// ---------------- host launcher ----------------
extern "C" void kernel_launch(void* const* d_in, const int* in_sizes, int n_in,
                              void* d_out, int out_size) {
    // Identify inputs by element count (all 7 distinct), robust to metadata order:
    //   x=N*128 (largest), edge_index=2E, edge_weight=E, W1=8192, W2=2560, b1=64, b2=40
    int order[16];
    for (int i = 0; i < n_in; i++) order[i] = i;
    for (int a = 0; a < n_in; a++)
        for (int bidx = a + 1; bidx < n_in; bidx++)
            if (in_sizes[order[bidx]] > in_sizes[order[a]]) {
                int t = order[a]; order[a] = order[bidx]; order[bidx] = t;
            }

    const float* x   = (const float*)d_in[order[0]];
    const int*   ei  = (const int*)  d_in[order[1]];   // int32 view; dtype sniffed on device
    const float* w   = (const float*)d_in[order[2]];
    const float* W1  = (const float*)d_in[order[3]];
    const float* W2  = (const float*)d_in[order[4]];
    const float* b1  = (const float*)d_in[order[5]];
    const float* b2  = (const float*)d_in[order[6]];
    float* out = (float*)d_out;

    int N = in_sizes[order[0]] / F0;   // 100000
    int E = in_sizes[order[2]];        // 1600000
    if (N > N_NODES) N = N_NODES;
    if (E > E_EDGES) E = E_EDGES;

    const int T = 256;
    int NB = (N + 1023) / 1024;

    k_sniff<<<1, 32>>>(ei);                                                  // 0
    k_edge_prep<<<(E + T - 1) / T, T>>>(ei, w, E, N);                        // 1
    k_scan1<<<NB, 1024>>>(N);                                                // 2
    k_gemm<F0, F1, 16><<<(N + 15) / 16, 16 * (F1 / 8)>>>(x, W1, g_h1, N);    // 3  <- ncu capture
    k_scan2<<<1, 128>>>(NB);                                                 // 4
    k_scan3<<<(N + T - 1) / T, T>>>(N, E);                                   // 5
    k_fill<<<(E + T - 1) / T, T>>>(w, E);                                    // 6
    k_gather_gemm2<<<(N + 15) / 16, 128>>>(g_h1, b1, W2, N);                 // 7
    k_gather2<<<(N * (F2 / 4) + T - 1) / T, T>>>(b2, out, N);                // 8
    k_finalize<<<(N + 3) / 4, dim3(32, 4)>>>(out, N);                        // 9
}